// round 16
// baseline (speedup 1.0000x reference)
#include <cuda_runtime.h>

// ---------------------------------------------------------------------------
// 2-level 3D inverse DWT (db4, mode='zero'): segmented z streaming pass, then
// fused y+x. y-stage reads GLOBAL directly (coalesced float2, no staging);
// x-stage: scalar rolling chunks with exact-fit chunk length per level
// (CH*NCH = N-3) -> single-pass dispatch, minimal LDS/pair.
// __launch_bounds__(256,8) pins k_yx at <=32 regs. float4 z-pass.
//
// Synthesis (L=8, conv_transpose stride 2, pad 6): out len M = 2n-6,
//   y[2p]   = sum_t x[p+t]*g[6-2t],  y[2p+1] = sum_t x[p+t]*g[7-2t]
// ---------------------------------------------------------------------------

#define G0_0 0.23037781330885523f
#define G0_1 0.7148465705525415f
#define G0_2 0.6308807679295904f
#define G0_3 (-0.02798376941698385f)
#define G0_4 (-0.18703481171888114f)
#define G0_5 0.030841381835986965f
#define G0_6 0.032883011666982945f
#define G0_7 (-0.010597401784997278f)

#define G1_0 (-0.010597401784997278f)
#define G1_1 (-0.032883011666982945f)
#define G1_2 0.030841381835986965f
#define G1_3 0.18703481171888114f
#define G1_4 (-0.02798376941698385f)
#define G1_5 (-0.6308807679295904f)
#define G1_6 0.7148465705525415f
#define G1_7 (-0.23037781330885523f)

__device__ __forceinline__ void sfb_pair(
    float l0, float l1, float l2, float l3,
    float h0, float h1, float h2, float h3,
    float& ye, float& yo)
{
    ye = fmaf(l0, G0_6,
         fmaf(l1, G0_4,
         fmaf(l2, G0_2,
         fmaf(l3, G0_0,
         fmaf(h0, G1_6,
         fmaf(h1, G1_4,
         fmaf(h2, G1_2,
              h3 * G1_0)))))));
    yo = fmaf(l0, G0_7,
         fmaf(l1, G0_5,
         fmaf(l2, G0_3,
         fmaf(l3, G0_1,
         fmaf(h0, G1_7,
         fmaf(h1, G1_5,
         fmaf(h2, G1_3,
              h3 * G1_1)))))));
}

__device__ __forceinline__ void sfb_pair2(
    float2 l0, float2 l1, float2 l2, float2 l3,
    float2 h0, float2 h1, float2 h2, float2 h3,
    float2& ye, float2& yo)
{
    sfb_pair(l0.x, l1.x, l2.x, l3.x, h0.x, h1.x, h2.x, h3.x, ye.x, yo.x);
    sfb_pair(l0.y, l1.y, l2.y, l3.y, h0.y, h1.y, h2.y, h3.y, ye.y, yo.y);
}

__device__ __forceinline__ void sfb_pair4(
    float4 l0, float4 l1, float4 l2, float4 l3,
    float4 h0, float4 h1, float4 h2, float4 h3,
    float4& ye, float4& yo)
{
    sfb_pair(l0.x, l1.x, l2.x, l3.x, h0.x, h1.x, h2.x, h3.x, ye.x, yo.x);
    sfb_pair(l0.y, l1.y, l2.y, l3.y, h0.y, h1.y, h2.y, h3.y, ye.y, yo.y);
    sfb_pair(l0.z, l1.z, l2.z, l3.z, h0.z, h1.z, h2.z, h3.z, ye.z, yo.z);
    sfb_pair(l0.w, l1.w, l2.w, l3.w, h0.w, h1.w, h2.w, h3.w, ye.w, yo.w);
}

// Scratch: z-pass output, level-2 max: 16 slices * 4 bands * 126 * 66*66
__device__ float g_mid[35126784];   // 140.5 MB
__device__ float g_LL1[4599936];    // 16 * 66^3 (18.4 MB)

// ---------------------------------------------------------------------------
// Kernel 1: z synthesis, SEGMENTED streaming lines, float4 over inner (y*x).
// 8 bands -> 4. Thread = (segment of PP pairs, float4 column). NSEG*PP = N-3.
// Output layout: [slice][b4][M_z][N^2].
// ---------------------------------------------------------------------------
template<int N, int NSEG, int PP>
__global__ void k_zpass(const float* __restrict__ lo_t,
                        const float* __restrict__ yh,
                        float* __restrict__ out)
{
    constexpr int N2  = N * N;
    constexpr int M   = 2 * N - 6;
    constexpr int S   = N2 / 4;          // float4 stride along z
    constexpr int VOL = N2 * N;
    constexpr int ITEMS = S * NSEG;

    int idx = blockIdx.x * blockDim.x + threadIdx.x;
    if (idx >= ITEMS) return;
    int i4  = idx % S;
    int seg = idx / S;
    int p0  = seg * PP;

    const int g = blockIdx.y;            // slice*4 + b4
    const int slice = g >> 2;
    const int b4 = g & 3;

    const float* lo_s = (b4 == 0) ? lo_t + slice * VOL
                                  : yh + (slice * 7 + (b4 - 1)) * VOL;
    const float* hi_s = yh + (slice * 7 + (b4 + 3)) * VOL;

    const float4* lp = (const float4*)lo_s + i4 + p0 * S;
    const float4* hp = (const float4*)hi_s + i4 + p0 * S;
    float4* op = (float4*)(out + g * M * N2) + i4 + 2 * p0 * S;

    float4 l0 = lp[0], l1 = lp[S], l2 = lp[2 * S];
    float4 h0 = hp[0], h1 = hp[S], h2 = hp[2 * S];
    lp += 3 * S; hp += 3 * S;

    #pragma unroll 3
    for (int p = 0; p < PP; p++) {
        float4 l3 = *lp, h3 = *hp;
        float4 ye, yo;
        sfb_pair4(l0, l1, l2, l3, h0, h1, h2, h3, ye, yo);
        op[0] = ye;
        op[S] = yo;
        l0 = l1; l1 = l2; l2 = l3;
        h0 = h1; h1 = h2; h2 = h3;
        lp += S; hp += S; op += 2 * S;
    }
}

// ---------------------------------------------------------------------------
// Kernel 2: fused y + x synthesis. 4 bands -> 1. Requires TY | (N-3) and
// CH*NCH == N-3; the y-window (TY+3 rows) is always in range -> NO memory
// bounds checks.
//   Block = (y-tile of TY pairs, oz, slice).  smem: s_mid [2][2*TY][N] ONLY.
//   y items: (j<2, q<NQ, x2<N/2), 3-pair rolling chunk, LOADS FROM GLOBAL
//            (adjacent x2 -> contiguous float2: fully coalesced LDG.64).
//   x items: (row<2*TY, c<NCH), exactly CH pairs rolling, scalar LDS.
// ---------------------------------------------------------------------------
#define K2_TPB 256

template<int N, int TY, int NQ, int NCH, int CH>
__global__ void __launch_bounds__(K2_TPB, 8)
k_yx(const float* __restrict__ in,
     float* __restrict__ out)
{
    constexpr int N2   = N * N;
    constexpr int M    = 2 * N - 6;
    constexpr int NH   = N / 2;
    constexpr int ROWS = 2 * TY;
    constexpr int MN2  = M * N2;          // band stride in MID
    constexpr int MVOL = M * M * M;

    extern __shared__ float sm[];
    float* s_mid = sm;                  // [2][ROWS][N]

    const int tid   = threadIdx.x;
    const int slice = blockIdx.z;
    const int oz    = blockIdx.y;
    const int py0   = blockIdx.x * TY;

    // ---- y synthesis from GLOBAL: bands (j, j+2) -> s_mid[j] ----
    {
        constexpr int YIT = 2 * NQ * NH;
        constexpr int KY = (YIT + K2_TPB - 1) / K2_TPB;
        const float* base = in + (slice * 4 * M + oz) * N2 + py0 * N;
        #pragma unroll
        for (int k = 0; k < KY; k++) {
            int idx = tid + k * K2_TPB;
            if (KY * K2_TPB == YIT || idx < YIT) {
                int x2 = idx % NH;
                int rr = idx / NH;
                int q  = rr % NQ;
                int j  = rr / NQ;
                int p0 = 3 * q;
                const float* lp = base + j * MN2 + p0 * N + 2 * x2;
                const float* hp = lp + 2 * MN2;
                float2 l0 = *(const float2*)(lp);
                float2 l1 = *(const float2*)(lp + N);
                float2 l2 = *(const float2*)(lp + 2 * N);
                float2 l3 = *(const float2*)(lp + 3 * N);
                float2 h0 = *(const float2*)(hp);
                float2 h1 = *(const float2*)(hp + N);
                float2 h2 = *(const float2*)(hp + 2 * N);
                float2 h3 = *(const float2*)(hp + 3 * N);
                float* op = s_mid + (j * ROWS + 2 * p0) * N + 2 * x2;
                float2 ye, yo;
                sfb_pair2(l0, l1, l2, l3, h0, h1, h2, h3, ye, yo);
                *(float2*)(op)     = ye;
                *(float2*)(op + N) = yo;
                if (p0 + 1 < TY) {
                    float2 l4 = *(const float2*)(lp + 4 * N);
                    float2 h4 = *(const float2*)(hp + 4 * N);
                    sfb_pair2(l1, l2, l3, l4, h1, h2, h3, h4, ye, yo);
                    *(float2*)(op + 2 * N) = ye;
                    *(float2*)(op + 3 * N) = yo;
                    if (p0 + 2 < TY) {
                        float2 l5 = *(const float2*)(lp + 5 * N);
                        float2 h5 = *(const float2*)(hp + 5 * N);
                        sfb_pair2(l2, l3, l4, l5, h2, h3, h4, h5, ye, yo);
                        *(float2*)(op + 4 * N) = ye;
                        *(float2*)(op + 5 * N) = yo;
                    }
                }
            }
        }
    }
    __syncthreads();

    // ---- x synthesis: item = (row, chunk of CH pairs), rolling, to global --
    // CH*NCH == N-3 exactly: no guards, single dispatch pass when XIT <= TPB.
    {
        constexpr int XIT = ROWS * NCH;
        constexpr int KX = (XIT + K2_TPB - 1) / K2_TPB;
        float* oslab = out + slice * MVOL + (oz * M + 2 * py0) * M;
        #pragma unroll
        for (int k = 0; k < KX; k++) {
            int idx = tid + k * K2_TPB;
            if (KX * K2_TPB == XIT || idx < XIT) {
                int c   = idx % NCH;
                int row = idx / NCH;
                int p0  = CH * c;
                const float* lp = s_mid + row * N + p0;
                const float* hp = lp + ROWS * N;
                float l0 = lp[0], l1 = lp[1], l2 = lp[2];
                float h0 = hp[0], h1 = hp[1], h2 = hp[2];
                float* o = oslab + row * M + 2 * p0;
                #pragma unroll
                for (int s = 0; s < CH; s++) {
                    float l3 = lp[3 + s], h3 = hp[3 + s];
                    float ye, yo;
                    sfb_pair(l0, l1, l2, l3, h0, h1, h2, h3, ye, yo);
                    *(float2*)(o + 2 * s) = make_float2(ye, yo);
                    l0 = l1; l1 = l2; l2 = l3;
                    h0 = h1; h1 = h2; h2 = h3;
                }
            }
        }
    }
}

extern "C" void kernel_launch(void* const* d_in, const int* in_sizes, int n_in,
                              void* d_out, int out_size)
{
    (void)in_sizes; (void)n_in; (void)out_size;

    const float* yl  = (const float*)d_in[0];  // (2,8,36,36,36)   16 slices
    const float* yh0 = (const float*)d_in[1];  // (2,8,7,66,66,66)
    const float* yh1 = (const float*)d_in[2];  // (2,8,7,36,36,36)
    float* out = (float*)d_out;                // (2,8,126,126,126)

    float *MID, *LL1;
    cudaGetSymbolAddress((void**)&MID, g_mid);
    cudaGetSymbolAddress((void**)&LL1, g_LL1);

    // ---------------- Level 1: n=36 -> 66 ----------------
    {
        constexpr int N = 36, M = 2 * N - 6;
        constexpr int ITEMS = (N * N / 4) * 3;       // NSEG=3, PP=11
        dim3 gz((ITEMS + 127) / 128, 64);
        k_zpass<N, 3, 11><<<gz, 128>>>(yl, yh1, MID);

        constexpr int TY = 11;                       // 33 = 3*11, NQ=4
        dim3 gyx((N - 3) / TY, M, 16);
        size_t sh = (size_t)(2 * (2 * TY) * N) * sizeof(float);
        // x-chunks: CH=3, NCH=11 (XIT = 22*11 = 242, single pass)
        k_yx<N, TY, 4, 11, 3><<<gyx, K2_TPB, sh>>>(MID, LL1);
    }

    // ---------------- Level 2: n=66 -> 126 ----------------
    {
        constexpr int N = 66, M = 2 * N - 6;
        constexpr int ITEMS = (N * N / 4) * 7;       // NSEG=7, PP=9 (R7-proven)
        dim3 gz((ITEMS + 127) / 128, 64);
        k_zpass<N, 7, 9><<<gz, 128>>>(LL1, yh0, MID);

        constexpr int TY = 9;                        // 63 = 7*9, NQ=3
        dim3 gyx((N - 3) / TY, M, 16);
        size_t sh = (size_t)(2 * (2 * TY) * N) * sizeof(float);
        // x-chunks: CH=7, NCH=9 (XIT = 18*9 = 162, single pass, 2.86 LDS/pair)
        k_yx<N, TY, 3, 9, 7><<<gyx, K2_TPB, sh>>>(MID, out);
    }
}

// round 17
// speedup vs baseline: 1.3935x; 1.3935x over previous
#include <cuda_runtime.h>
#include <cuda_fp16.h>

// ---------------------------------------------------------------------------
// 2-level 3D inverse DWT (db4, mode='zero'): segmented z streaming pass, then
// fused y+x. The z->yx intermediate (MID) is stored in FP16 (packed half2):
// internal-only data, ~2^-11 relative quantization propagating linearly ->
// final rel_err ~2e-4 << 1e-3 gate, and MID DRAM traffic is halved.
// y-stage reads MID directly (coalesced half2); x-stage scalar rolling
// 3-pair chunks (measured optimum). __launch_bounds__(256,8). float4 z-loads.
//
// Synthesis (L=8, conv_transpose stride 2, pad 6): out len M = 2n-6,
//   y[2p]   = sum_t x[p+t]*g[6-2t],  y[2p+1] = sum_t x[p+t]*g[7-2t]
// ---------------------------------------------------------------------------

#define G0_0 0.23037781330885523f
#define G0_1 0.7148465705525415f
#define G0_2 0.6308807679295904f
#define G0_3 (-0.02798376941698385f)
#define G0_4 (-0.18703481171888114f)
#define G0_5 0.030841381835986965f
#define G0_6 0.032883011666982945f
#define G0_7 (-0.010597401784997278f)

#define G1_0 (-0.010597401784997278f)
#define G1_1 (-0.032883011666982945f)
#define G1_2 0.030841381835986965f
#define G1_3 0.18703481171888114f
#define G1_4 (-0.02798376941698385f)
#define G1_5 (-0.6308807679295904f)
#define G1_6 0.7148465705525415f
#define G1_7 (-0.23037781330885523f)

__device__ __forceinline__ void sfb_pair(
    float l0, float l1, float l2, float l3,
    float h0, float h1, float h2, float h3,
    float& ye, float& yo)
{
    ye = fmaf(l0, G0_6,
         fmaf(l1, G0_4,
         fmaf(l2, G0_2,
         fmaf(l3, G0_0,
         fmaf(h0, G1_6,
         fmaf(h1, G1_4,
         fmaf(h2, G1_2,
              h3 * G1_0)))))));
    yo = fmaf(l0, G0_7,
         fmaf(l1, G0_5,
         fmaf(l2, G0_3,
         fmaf(l3, G0_1,
         fmaf(h0, G1_7,
         fmaf(h1, G1_5,
         fmaf(h2, G1_3,
              h3 * G1_1)))))));
}

__device__ __forceinline__ void sfb_pair2(
    float2 l0, float2 l1, float2 l2, float2 l3,
    float2 h0, float2 h1, float2 h2, float2 h3,
    float2& ye, float2& yo)
{
    sfb_pair(l0.x, l1.x, l2.x, l3.x, h0.x, h1.x, h2.x, h3.x, ye.x, yo.x);
    sfb_pair(l0.y, l1.y, l2.y, l3.y, h0.y, h1.y, h2.y, h3.y, ye.y, yo.y);
}

__device__ __forceinline__ void sfb_pair4(
    float4 l0, float4 l1, float4 l2, float4 l3,
    float4 h0, float4 h1, float4 h2, float4 h3,
    float4& ye, float4& yo)
{
    sfb_pair(l0.x, l1.x, l2.x, l3.x, h0.x, h1.x, h2.x, h3.x, ye.x, yo.x);
    sfb_pair(l0.y, l1.y, l2.y, l3.y, h0.y, h1.y, h2.y, h3.y, ye.y, yo.y);
    sfb_pair(l0.z, l1.z, l2.z, l3.z, h0.z, h1.z, h2.z, h3.z, ye.z, yo.z);
    sfb_pair(l0.w, l1.w, l2.w, l3.w, h0.w, h1.w, h2.w, h3.w, ye.w, yo.w);
}

// Scratch: MID in FP16. Level-2 max: 16 slices * 4 bands * 126 * 66*66 halves
// = 35,126,784 halves (70.3 MB). LL1 stays fp32 (feeds z-pass float4 loads).
__device__ __half g_mid[35126784];
__device__ float  g_LL1[4599936];    // 16 * 66^3 (18.4 MB)

// ---------------------------------------------------------------------------
// Kernel 1: z synthesis, SEGMENTED streaming lines, float4 loads over inner
// (y*x), packed half2 stores. 8 bands -> 4. Thread = (segment of PP pairs,
// float4 column). NSEG*PP = N-3. Output layout: [slice][b4][M_z][N^2] halves.
// ---------------------------------------------------------------------------
template<int N, int NSEG, int PP>
__global__ void k_zpass(const float* __restrict__ lo_t,
                        const float* __restrict__ yh,
                        __half* __restrict__ out)
{
    constexpr int N2  = N * N;
    constexpr int M   = 2 * N - 6;
    constexpr int S   = N2 / 4;          // float4 stride along z (loads)
    constexpr int S2  = N2 / 2;          // half2 stride along z (stores)
    constexpr int VOL = N2 * N;
    constexpr int ITEMS = S * NSEG;

    int idx = blockIdx.x * blockDim.x + threadIdx.x;
    if (idx >= ITEMS) return;
    int i4  = idx % S;
    int seg = idx / S;
    int p0  = seg * PP;

    const int g = blockIdx.y;            // slice*4 + b4
    const int slice = g >> 2;
    const int b4 = g & 3;

    const float* lo_s = (b4 == 0) ? lo_t + slice * VOL
                                  : yh + (slice * 7 + (b4 - 1)) * VOL;
    const float* hi_s = yh + (slice * 7 + (b4 + 3)) * VOL;

    const float4* lp = (const float4*)lo_s + i4 + p0 * S;
    const float4* hp = (const float4*)hi_s + i4 + p0 * S;
    __half2* op = (__half2*)(out + (size_t)g * M * N2) + 2 * i4 + 2 * p0 * S2;

    float4 l0 = lp[0], l1 = lp[S], l2 = lp[2 * S];
    float4 h0 = hp[0], h1 = hp[S], h2 = hp[2 * S];
    lp += 3 * S; hp += 3 * S;

    #pragma unroll 3
    for (int p = 0; p < PP; p++) {
        float4 l3 = *lp, h3 = *hp;
        float4 ye, yo;
        sfb_pair4(l0, l1, l2, l3, h0, h1, h2, h3, ye, yo);
        op[0]      = __floats2half2_rn(ye.x, ye.y);
        op[1]      = __floats2half2_rn(ye.z, ye.w);
        op[S2]     = __floats2half2_rn(yo.x, yo.y);
        op[S2 + 1] = __floats2half2_rn(yo.z, yo.w);
        l0 = l1; l1 = l2; l2 = l3;
        h0 = h1; h1 = h2; h2 = h3;
        lp += S; hp += S; op += 2 * S2;
    }
}

// ---------------------------------------------------------------------------
// Kernel 2: fused y + x synthesis. 4 bands -> 1. Requires TY | (N-3); the
// y-window (TY+3 rows) is always in range -> NO memory bounds checks.
//   Block = (y-tile of TY pairs, oz, slice).  smem: s_mid [2][2*TY][N] (f32).
//   y items: (j<2, q<NQ, x2<N/2), 3-pair rolling chunk, LOADS MID AS half2
//            (adjacent x2 -> contiguous: fully coalesced LDG.32).
//   x items: (row<2*TY, c<NCH), exactly 3 pairs rolling, scalar LDS, f32 out.
// ---------------------------------------------------------------------------
#define K2_TPB 256

template<int N, int TY, int NQ, int NCH>
__global__ void __launch_bounds__(K2_TPB, 8)
k_yx(const __half* __restrict__ in,
     float* __restrict__ out)
{
    constexpr int N2   = N * N;
    constexpr int M    = 2 * N - 6;
    constexpr int NH   = N / 2;           // half2 per row
    constexpr int ROWS = 2 * TY;
    constexpr int MN2H = (M * N2) / 2;    // band stride in MID, half2 units
    constexpr int MVOL = M * M * M;

    extern __shared__ float sm[];
    float* s_mid = sm;                  // [2][ROWS][N]

    const int tid   = threadIdx.x;
    const int slice = blockIdx.z;
    const int oz    = blockIdx.y;
    const int py0   = blockIdx.x * TY;

    // ---- y synthesis from MID (half2): bands (j, j+2) -> s_mid[j] ----
    {
        constexpr int YIT = 2 * NQ * NH;
        constexpr int KY = (YIT + K2_TPB - 1) / K2_TPB;
        const __half2* base = (const __half2*)in
            + ((((size_t)slice * 4 * M + oz) * N2 + (size_t)py0 * N) >> 1);
        #pragma unroll
        for (int k = 0; k < KY; k++) {
            int idx = tid + k * K2_TPB;
            if (KY * K2_TPB == YIT || idx < YIT) {
                int x2 = idx % NH;
                int rr = idx / NH;
                int q  = rr % NQ;
                int j  = rr / NQ;
                int p0 = 3 * q;
                const __half2* lp = base + j * MN2H + p0 * NH + x2;
                const __half2* hp = lp + 2 * MN2H;
                float2 l0 = __half22float2(lp[0]);
                float2 l1 = __half22float2(lp[NH]);
                float2 l2 = __half22float2(lp[2 * NH]);
                float2 l3 = __half22float2(lp[3 * NH]);
                float2 h0 = __half22float2(hp[0]);
                float2 h1 = __half22float2(hp[NH]);
                float2 h2 = __half22float2(hp[2 * NH]);
                float2 h3 = __half22float2(hp[3 * NH]);
                float* op = s_mid + (j * ROWS + 2 * p0) * N + 2 * x2;
                float2 ye, yo;
                sfb_pair2(l0, l1, l2, l3, h0, h1, h2, h3, ye, yo);
                *(float2*)(op)     = ye;
                *(float2*)(op + N) = yo;
                if (p0 + 1 < TY) {
                    float2 l4 = __half22float2(lp[4 * NH]);
                    float2 h4 = __half22float2(hp[4 * NH]);
                    sfb_pair2(l1, l2, l3, l4, h1, h2, h3, h4, ye, yo);
                    *(float2*)(op + 2 * N) = ye;
                    *(float2*)(op + 3 * N) = yo;
                    if (p0 + 2 < TY) {
                        float2 l5 = __half22float2(lp[5 * NH]);
                        float2 h5 = __half22float2(hp[5 * NH]);
                        sfb_pair2(l2, l3, l4, l5, h2, h3, h4, h5, ye, yo);
                        *(float2*)(op + 4 * N) = ye;
                        *(float2*)(op + 5 * N) = yo;
                    }
                }
            }
        }
    }
    __syncthreads();

    // ---- x synthesis: item = (row, chunk of 3 pairs), rolling, to global ----
    {
        constexpr int XIT = ROWS * NCH;
        constexpr int KX = (XIT + K2_TPB - 1) / K2_TPB;
        float* oslab = out + (size_t)slice * MVOL + ((size_t)oz * M + 2 * py0) * M;
        #pragma unroll
        for (int k = 0; k < KX; k++) {
            int idx = tid + k * K2_TPB;
            if (KX * K2_TPB == XIT || idx < XIT) {
                int c   = idx % NCH;
                int row = idx / NCH;
                int p0  = 3 * c;
                const float* lp = s_mid + row * N + p0;
                const float* hp = lp + ROWS * N;
                float l0 = lp[0], l1 = lp[1], l2 = lp[2];
                float h0 = hp[0], h1 = hp[1], h2 = hp[2];
                float* o = oslab + row * M + 2 * p0;
                #pragma unroll
                for (int s = 0; s < 3; s++) {
                    float l3 = lp[3 + s], h3 = hp[3 + s];
                    float ye, yo;
                    sfb_pair(l0, l1, l2, l3, h0, h1, h2, h3, ye, yo);
                    *(float2*)(o + 2 * s) = make_float2(ye, yo);
                    l0 = l1; l1 = l2; l2 = l3;
                    h0 = h1; h1 = h2; h2 = h3;
                }
            }
        }
    }
}

extern "C" void kernel_launch(void* const* d_in, const int* in_sizes, int n_in,
                              void* d_out, int out_size)
{
    (void)in_sizes; (void)n_in; (void)out_size;

    const float* yl  = (const float*)d_in[0];  // (2,8,36,36,36)   16 slices
    const float* yh0 = (const float*)d_in[1];  // (2,8,7,66,66,66)
    const float* yh1 = (const float*)d_in[2];  // (2,8,7,36,36,36)
    float* out = (float*)d_out;                // (2,8,126,126,126)

    __half* MID;
    float* LL1;
    cudaGetSymbolAddress((void**)&MID, g_mid);
    cudaGetSymbolAddress((void**)&LL1, g_LL1);

    // ---------------- Level 1: n=36 -> 66 ----------------
    {
        constexpr int N = 36, M = 2 * N - 6;
        constexpr int ITEMS = (N * N / 4) * 3;       // NSEG=3, PP=11
        dim3 gz((ITEMS + 127) / 128, 64);
        k_zpass<N, 3, 11><<<gz, 128>>>(yl, yh1, MID);

        constexpr int TY = 11;                       // 33 = 3*11, NQ=4, NCH=11
        dim3 gyx((N - 3) / TY, M, 16);
        size_t sh = (size_t)(2 * (2 * TY) * N) * sizeof(float);
        k_yx<N, TY, 4, 11><<<gyx, K2_TPB, sh>>>(MID, LL1);
    }

    // ---------------- Level 2: n=66 -> 126 ----------------
    {
        constexpr int N = 66, M = 2 * N - 6;
        constexpr int ITEMS = (N * N / 4) * 7;       // NSEG=7, PP=9 (R7-proven)
        dim3 gz((ITEMS + 127) / 128, 64);
        k_zpass<N, 7, 9><<<gz, 128>>>(LL1, yh0, MID);

        constexpr int TY = 9;                        // 63 = 7*9, NQ=3, NCH=21
        dim3 gyx((N - 3) / TY, M, 16);
        size_t sh = (size_t)(2 * (2 * TY) * N) * sizeof(float);
        k_yx<N, TY, 3, 21><<<gyx, K2_TPB, sh>>>(MID, out);
    }
}